// round 3
// baseline (speedup 1.0000x reference)
#include <cuda_runtime.h>
#include <cstdint>
#include <float.h>
#include <math.h>

#define Bn 8
#define Tn 4096
#define Dn 512
#define Rn 1024
#define T2 2048      // #src = #dst pairs
#define Cn 3072      // kept tokens = Tn - Rn

// ---------------- scratch (device globals; no allocation allowed) -------------
__device__ float g_inv[Bn * Tn];                 // 1/||x[b,t]||
__device__ float g_best[Bn * T2];                // best score per src
__device__ int   g_barg[Bn * T2];                // argmax dst (local 0..2047)
__device__ int   g_srctok[Bn * Rn];              // rank -> src token index
__device__ int   g_dsttok[Bn * Rn];              // rank -> dst token index
__device__ int   g_winner[Bn * T2];              // dst_local -> winning rank (max), -1 none
__device__ unsigned char g_merged[Bn * Tn];      // merged_away mask
__device__ int   g_col[Bn * Cn];                 // compact idx -> token
__device__ float g_A[(size_t)Bn * Cn * Dn];      // merged matrix (GEMM A), 48 MB

// ---------------- K1: inverse norms ----------------
__global__ void k_norms(const float* __restrict__ x) {
    int row = blockIdx.x * 8 + (threadIdx.x >> 5);
    int lane = threadIdx.x & 31;
    const float4* p = (const float4*)(x + (size_t)row * Dn);
    float ss = 0.f;
#pragma unroll
    for (int i = 0; i < 4; i++) {
        float4 v = p[lane + 32 * i];
        ss += v.x * v.x + v.y * v.y + v.z * v.z + v.w * v.w;
    }
#pragma unroll
    for (int o = 16; o; o >>= 1) ss += __shfl_xor_sync(0xFFFFFFFFu, ss, o);
    if (lane == 0) g_inv[row] = 1.0f / fmaxf(sqrtf(ss), 1e-12f);
}

// ---------------- K2: scores GEMM with fused row max/argmax ----------------
// Block: 64 src rows; loops all 2048 dst in 128-wide tiles; K tiled by 16.
__global__ __launch_bounds__(256) void k_scores(const float* __restrict__ x) {
    const int b  = blockIdx.y;
    const int m0 = blockIdx.x * 64;
    __shared__ float As[16][64];
    __shared__ float Bs[16][128];
    __shared__ float s_cn[128];
    __shared__ float s_max[64];
    __shared__ int   s_arg[64];

    const int tid = threadIdx.x;
    const int tx = tid & 15, ty = tid >> 4;
    if (tid < 64) { s_max[tid] = -FLT_MAX; s_arg[tid] = 0; }

    const float* xb = x + (size_t)b * Tn * Dn;
    const int a_r = tid >> 2;            // 0..63
    const int a_k = (tid & 3) * 4;
    const float* aptr = xb + (size_t)(2 * (m0 + a_r) + 1) * Dn + a_k;
    const int b_r = tid >> 2;            // 0..63, plus +64 row
    const int b_k = (tid & 3) * 4;

    float acc[4][8];

    for (int nt = 0; nt < 16; ++nt) {
        const int n0 = nt * 128;
        __syncthreads();                     // protect s_cn, s_max reads from prev iter
        if (tid < 128) s_cn[tid] = g_inv[b * Tn + 2 * (n0 + tid)];
#pragma unroll
        for (int i = 0; i < 4; i++)
#pragma unroll
            for (int j = 0; j < 8; j++) acc[i][j] = 0.f;

        const float* bptr = xb + (size_t)(2 * (n0 + b_r)) * Dn + b_k;

        for (int kt = 0; kt < Dn; kt += 16) {
            float4 av  = *(const float4*)(aptr + kt);
            float4 bv0 = *(const float4*)(bptr + kt);
            float4 bv1 = *(const float4*)(bptr + (size_t)128 * Dn + kt);
            __syncthreads();
            As[a_k + 0][a_r] = av.x;  As[a_k + 1][a_r] = av.y;
            As[a_k + 2][a_r] = av.z;  As[a_k + 3][a_r] = av.w;
            Bs[b_k + 0][b_r] = bv0.x; Bs[b_k + 1][b_r] = bv0.y;
            Bs[b_k + 2][b_r] = bv0.z; Bs[b_k + 3][b_r] = bv0.w;
            Bs[b_k + 0][b_r + 64] = bv1.x; Bs[b_k + 1][b_r + 64] = bv1.y;
            Bs[b_k + 2][b_r + 64] = bv1.z; Bs[b_k + 3][b_r + 64] = bv1.w;
            __syncthreads();
#pragma unroll
            for (int k = 0; k < 16; k++) {
                float4 a4 = *(const float4*)(&As[k][ty * 4]);
                float4 b0 = *(const float4*)(&Bs[k][tx * 8]);
                float4 b1 = *(const float4*)(&Bs[k][tx * 8 + 4]);
                float ar[4] = {a4.x, a4.y, a4.z, a4.w};
                float br[8] = {b0.x, b0.y, b0.z, b0.w, b1.x, b1.y, b1.z, b1.w};
#pragma unroll
                for (int i = 0; i < 4; i++)
#pragma unroll
                    for (int j = 0; j < 8; j++)
                        acc[i][j] = fmaf(ar[i], br[j], acc[i][j]);
            }
        }
        // scale by dst inv-norm, reduce max/argmax (first-occurrence ties)
#pragma unroll
        for (int i = 0; i < 4; i++) {
            float best = -FLT_MAX; int barg = 0x7FFFFFFF;
#pragma unroll
            for (int j = 0; j < 8; j++) {
                float v = acc[i][j] * s_cn[tx * 8 + j];
                int c = n0 + tx * 8 + j;
                if (v > best || (v == best && c < barg)) { best = v; barg = c; }
            }
#pragma unroll
            for (int o = 8; o; o >>= 1) {
                float ov = __shfl_xor_sync(0xFFFFFFFFu, best, o);
                int   oc = __shfl_xor_sync(0xFFFFFFFFu, barg, o);
                if (ov > best || (ov == best && oc < barg)) { best = ov; barg = oc; }
            }
            if (tx == 0) {
                int r = ty * 4 + i;
                if (best > s_max[r] || (best == s_max[r] && barg < s_arg[r])) {
                    s_max[r] = best; s_arg[r] = barg;
                }
            }
        }
    }
    __syncthreads();
    if (tid < 64) {
        int s = m0 + tid;
        g_best[b * T2 + s] = s_max[tid] * g_inv[b * Tn + 2 * s + 1];
        g_barg[b * T2 + s] = s_arg[tid];
    }
}

// ---------------- K3: per-batch bitonic sort -> top-k, winner, mask ----------------
__global__ void k_topk() {
    const int b = blockIdx.x;
    __shared__ unsigned long long keys[T2];
    const int tid = threadIdx.x; // 1024 threads
    g_winner[b * T2 + tid] = -1;
    g_winner[b * T2 + tid + 1024] = -1;
    for (int t = tid; t < Tn; t += 1024) g_merged[b * Tn + t] = 0;
    for (int i = tid; i < T2; i += 1024) {
        unsigned u = __float_as_uint(g_best[b * T2 + i]);
        u = (u & 0x80000000u) ? ~u : (u | 0x80000000u); // ascending-monotone
        u = ~u;                                          // descending score
        keys[i] = ((unsigned long long)u << 32) | (unsigned)i;
    }
    __syncthreads();
    for (int k2 = 2; k2 <= T2; k2 <<= 1) {
        for (int j = k2 >> 1; j > 0; j >>= 1) {
            for (int i = tid; i < T2; i += 1024) {
                int ixj = i ^ j;
                if (ixj > i) {
                    bool up = ((i & k2) == 0);
                    unsigned long long a = keys[i], c = keys[ixj];
                    if ((a > c) == up) { keys[i] = c; keys[ixj] = a; }
                }
            }
            __syncthreads();
        }
    }
    if (tid < Rn) {
        int s = (int)(keys[tid] & 0xFFFFFFFFu);
        int stok = 2 * s + 1;
        int dloc = g_barg[b * T2 + s];
        g_srctok[b * Rn + tid] = stok;
        g_dsttok[b * Rn + tid] = 2 * dloc;
        g_merged[b * Tn + stok] = 1;
        atomicMax(&g_winner[b * T2 + dloc], tid);  // last update (max rank) wins
    }
}

// ---------------- K4: compaction (stable argsort of mask) ----------------
__global__ void k_scan() {
    const int b = blockIdx.x;
    __shared__ int sums[1024];
    const int tid = threadIdx.x;
    const int base = tid * 4;
    int loc[4]; int c0 = 0;
#pragma unroll
    for (int i = 0; i < 4; i++) { loc[i] = g_merged[b * Tn + base + i] ? 0 : 1; c0 += loc[i]; }
    sums[tid] = c0; __syncthreads();
    for (int off = 1; off < 1024; off <<= 1) {
        int v = (tid >= off) ? sums[tid - off] : 0;
        __syncthreads();
        sums[tid] += v;
        __syncthreads();
    }
    int run = (tid == 0) ? 0 : sums[tid - 1];
#pragma unroll
    for (int i = 0; i < 4; i++) {
        if (loc[i]) { g_col[b * Cn + run] = base + i; run++; }
    }
}

// ---------------- K5: build merged A matrix ----------------
__global__ void k_build(const float* __restrict__ x) {
    const int b = blockIdx.y, c = blockIdx.x;
    const int t = g_col[b * Cn + c];
    const int tid = threadIdx.x; // 128
    const float* xb = x + (size_t)b * Tn * Dn;
    float4 v = *(const float4*)(xb + (size_t)t * Dn + tid * 4);
    if ((t & 1) == 0) {
        int w = g_winner[b * T2 + (t >> 1)];
        if (w >= 0) {
            int mt = g_srctok[b * Rn + w];
            float4 u = *(const float4*)(xb + (size_t)mt * Dn + tid * 4);
            v.x = (u.x + v.x) * 0.5f; v.y = (u.y + v.y) * 0.5f;
            v.z = (u.z + v.z) * 0.5f; v.w = (u.w + v.w) * 0.5f;
        }
    }
    *(float4*)(g_A + ((size_t)b * Cn + c) * Dn + tid * 4) = v;
}

// ---------------- K6: hidden = A @ W + bias, scattered to out rows ----------------
__global__ __launch_bounds__(256) void k_gemm(const float* __restrict__ W,
                                              const float* __restrict__ bias,
                                              float* __restrict__ out) {
    const int nt = blockIdx.x;     // 0..3 (N tiles of 128)
    const int mt = blockIdx.y;     // 0..191 (M tiles of 128)
    __shared__ float As[16][128];
    __shared__ float Bs[16][128];
    __shared__ float s_bias[128];
    __shared__ int   s_tok[128];

    const int tid = threadIdx.x;
    const int tx = tid & 15, ty = tid >> 4;
    const int m0 = mt * 128;
    const int b  = m0 / Cn;              // 3072 % 128 == 0: tile never crosses batch
    const int cm0 = m0 % Cn;
    if (tid < 128) {
        s_bias[tid] = bias[nt * 128 + tid];
        s_tok[tid]  = g_col[b * Cn + cm0 + tid];
    }
    const float* Abase = g_A + (size_t)m0 * Dn;
    const int a_r = tid >> 2, a_k = (tid & 3) * 4;
    const int w_r = tid >> 5, w_n = (tid & 31) * 4;

    float acc[8][8];
#pragma unroll
    for (int i = 0; i < 8; i++)
#pragma unroll
        for (int j = 0; j < 8; j++) acc[i][j] = 0.f;

    for (int kt = 0; kt < Dn; kt += 16) {
        float4 a0 = *(const float4*)(Abase + (size_t)a_r * Dn + kt + a_k);
        float4 a1 = *(const float4*)(Abase + (size_t)(a_r + 64) * Dn + kt + a_k);
        float4 w0 = *(const float4*)(W + (size_t)(kt + w_r) * Dn + nt * 128 + w_n);
        float4 w1 = *(const float4*)(W + (size_t)(kt + w_r + 8) * Dn + nt * 128 + w_n);
        __syncthreads();
        As[a_k + 0][a_r] = a0.x; As[a_k + 1][a_r] = a0.y;
        As[a_k + 2][a_r] = a0.z; As[a_k + 3][a_r] = a0.w;
        As[a_k + 0][a_r + 64] = a1.x; As[a_k + 1][a_r + 64] = a1.y;
        As[a_k + 2][a_r + 64] = a1.z; As[a_k + 3][a_r + 64] = a1.w;
        *(float4*)&Bs[w_r][w_n]     = w0;
        *(float4*)&Bs[w_r + 8][w_n] = w1;
        __syncthreads();
#pragma unroll
        for (int k = 0; k < 16; k++) {
            float4 av0 = *(const float4*)&As[k][ty * 8];
            float4 av1 = *(const float4*)&As[k][ty * 8 + 4];
            float4 bv0 = *(const float4*)&Bs[k][tx * 8];
            float4 bv1 = *(const float4*)&Bs[k][tx * 8 + 4];
            float ar[8] = {av0.x, av0.y, av0.z, av0.w, av1.x, av1.y, av1.z, av1.w};
            float br[8] = {bv0.x, bv0.y, bv0.z, bv0.w, bv1.x, bv1.y, bv1.z, bv1.w};
#pragma unroll
            for (int i = 0; i < 8; i++)
#pragma unroll
                for (int j = 0; j < 8; j++)
                    acc[i][j] = fmaf(ar[i], br[j], acc[i][j]);
        }
    }
    float* ob = out + (size_t)b * Tn * Dn + nt * 128;
#pragma unroll
    for (int i = 0; i < 8; i++) {
        int r = ty * 8 + i;
        int t = s_tok[r];
        float* op = ob + (size_t)t * Dn + tx * 8;
        float4 o0, o1;
        o0.x = acc[i][0] + s_bias[tx * 8 + 0]; o0.y = acc[i][1] + s_bias[tx * 8 + 1];
        o0.z = acc[i][2] + s_bias[tx * 8 + 2]; o0.w = acc[i][3] + s_bias[tx * 8 + 3];
        o1.x = acc[i][4] + s_bias[tx * 8 + 4]; o1.y = acc[i][5] + s_bias[tx * 8 + 5];
        o1.z = acc[i][6] + s_bias[tx * 8 + 6]; o1.w = acc[i][7] + s_bias[tx * 8 + 7];
        *(float4*)op       = o0;
        *(float4*)(op + 4) = o1;
    }
}

// ---------------- K7: out[src] = out[dst] ----------------
__global__ void k_copy(float* __restrict__ out) {
    const int b = blockIdx.y, i = blockIdx.x;
    const int st = g_srctok[b * Rn + i], dt = g_dsttok[b * Rn + i];
    const int tid = threadIdx.x; // 128
    const float4* src = (const float4*)(out + (size_t)b * Tn * Dn + (size_t)dt * Dn);
    float4* dst = (float4*)(out + (size_t)b * Tn * Dn + (size_t)st * Dn);
    dst[tid] = src[tid];
}

extern "C" void kernel_launch(void* const* d_in, const int* in_sizes, int n_in,
                              void* d_out, int out_size) {
    const float* x    = (const float*)d_in[0];
    const float* W    = (const float*)d_in[1];
    const float* bias = (const float*)d_in[2];
    float* out = (float*)d_out;

    k_norms<<<Bn * Tn / 8, 256>>>(x);
    dim3 g2(T2 / 64, Bn);
    k_scores<<<g2, 256>>>(x);
    k_topk<<<Bn, 1024>>>();
    k_scan<<<Bn, 1024>>>();
    dim3 g5(Cn, Bn);
    k_build<<<g5, 128>>>(x);
    dim3 g6(Dn / 128, (Bn * Cn) / 128);
    k_gemm<<<g6, 256>>>(W, bias, out);
    dim3 g7(Rn, Bn);
    k_copy<<<g7, 128>>>(out);
}

// round 5
// speedup vs baseline: 3.5142x; 3.5142x over previous
#include <cuda_runtime.h>
#include <cuda_fp16.h>
#include <cstdint>
#include <float.h>
#include <math.h>

#define Bn 8
#define Tn 4096
#define Dn 512
#define Rn 1024
#define T2 2048
#define Cn 3072
#define KP 1536
#define NSTAGE 24                 // KP / 64
#define TILE_BYTES 16384          // 128 rows x 128B
#define SMEM_MAIN (4 * TILE_BYTES)  // A0 B0 A1 B1
#define SMEM_DYN (SMEM_MAIN + 1024)

// ---------------- device scratch ----------------
__device__ __align__(16) unsigned short g_S [(size_t)Bn * T2 * KP];  // src aug fp16 [H,H,M]
__device__ __align__(16) unsigned short g_Dm[(size_t)Bn * T2 * KP];  // dst aug fp16 [H,M,H]
__device__ __align__(16) unsigned short g_A2[(size_t)Bn * Cn * KP];  // merged aug [H,H,M]
__device__ __align__(16) unsigned short g_Wt[(size_t)Dn * KP];       // W^T aug [H,M,H]
__device__ unsigned long long g_key[Bn * T2];
__device__ int   g_barg[Bn * T2];
__device__ int   g_srctok[Bn * Rn];
__device__ int   g_dsttok[Bn * Rn];
__device__ int   g_winner[Bn * T2];
__device__ unsigned char g_merged[Bn * Tn];
__device__ int   g_col[Bn * Cn];

// ---------------- helpers ----------------
__device__ __forceinline__ uint32_t smem_u32(const void* p) {
    uint32_t a;
    asm("{ .reg .u64 t; cvta.to.shared.u64 t, %1; cvt.u32.u64 %0, t; }" : "=r"(a) : "l"(p));
    return a;
}
__device__ __forceinline__ void cp16(uint32_t dst, const void* src) {
    asm volatile("cp.async.cg.shared.global [%0], [%1], 16;\n" :: "r"(dst), "l"(src));
}
#define CP_COMMIT() asm volatile("cp.async.commit_group;\n" ::: "memory")
#define CP_WAIT1()  asm volatile("cp.async.wait_group 1;\n" ::: "memory")
__device__ __forceinline__ void ldm_x4(uint32_t a, uint32_t& r0, uint32_t& r1,
                                       uint32_t& r2, uint32_t& r3) {
    asm volatile("ldmatrix.sync.aligned.m8n8.x4.shared.b16 {%0,%1,%2,%3}, [%4];\n"
        : "=r"(r0), "=r"(r1), "=r"(r2), "=r"(r3) : "r"(a));
}
__device__ __forceinline__ void mma16816(float* c, const uint32_t* a, uint32_t b0, uint32_t b1) {
    asm volatile("mma.sync.aligned.m16n8k16.row.col.f32.f16.f16.f32 "
        "{%0,%1,%2,%3}, {%4,%5,%6,%7}, {%8,%9}, {%0,%1,%2,%3};\n"
        : "+f"(c[0]), "+f"(c[1]), "+f"(c[2]), "+f"(c[3])
        : "r"(a[0]), "r"(a[1]), "r"(a[2]), "r"(a[3]), "r"(b0), "r"(b1));
}

// ---------------- K1: norms + fp16 split of normalized rows ----------------
__global__ void k_prep(const float* __restrict__ x) {
    int row = blockIdx.x * 8 + (threadIdx.x >> 5);
    int lane = threadIdx.x & 31;
    int b = row >> 12, t = row & 4095;
    const float4* p = (const float4*)(x + (size_t)row * Dn);
    float4 v[4]; float ss = 0.f;
#pragma unroll
    for (int i = 0; i < 4; i++) {
        v[i] = p[lane + 32 * i];
        ss += v[i].x * v[i].x + v[i].y * v[i].y + v[i].z * v[i].z + v[i].w * v[i].w;
    }
#pragma unroll
    for (int o = 16; o; o >>= 1) ss += __shfl_xor_sync(0xFFFFFFFFu, ss, o);
    float sc = 1024.0f / fmaxf(sqrtf(ss), 1e-12f);
    int odd = t & 1, s = t >> 1;
    unsigned short* rp = (odd ? g_S : g_Dm) + ((size_t)(b * T2 + s)) * KP;
    int moff = odd ? 1024 : 512;
    int h2off = odd ? 512 : 1024;
    if (odd && lane == 0) g_key[b * T2 + s] = 0ull;
#pragma unroll
    for (int i = 0; i < 4; i++) {
        int k0 = 4 * (lane + 32 * i);
        float a[4] = {v[i].x * sc, v[i].y * sc, v[i].z * sc, v[i].w * sc};
        unsigned short hs[4], ms[4];
#pragma unroll
        for (int j = 0; j < 4; j++) {
            __half hh = __float2half_rn(a[j]);
            hs[j] = __half_as_ushort(hh);
            ms[j] = __half_as_ushort(__float2half_rn(a[j] - __half2float(hh)));
        }
        ushort4 h4 = make_ushort4(hs[0], hs[1], hs[2], hs[3]);
        ushort4 m4 = make_ushort4(ms[0], ms[1], ms[2], ms[3]);
        *(ushort4*)(rp + k0)         = h4;
        *(ushort4*)(rp + h2off + k0) = h4;
        *(ushort4*)(rp + moff + k0)  = m4;
    }
}

// ---------------- K2: W^T aug split ----------------
__global__ void k_wprep(const float* __restrict__ W) {
    int n = blockIdx.x;
    for (int k = threadIdx.x; k < Dn; k += 256) {
        float w = W[(size_t)k * Dn + n];
        __half hh = __float2half_rn(w);
        unsigned short h = __half_as_ushort(hh);
        unsigned short m = __half_as_ushort(__float2half_rn(w - __half2float(hh)));
        size_t base = (size_t)n * KP;
        g_Wt[base + k] = h; g_Wt[base + 512 + k] = m; g_Wt[base + 1024 + k] = h;
    }
}

// ---------------- HMMA tile engine: C[128x128] = A[128xKP] * B[128xKP]^T ----------------
__device__ __forceinline__ void load_stage(const unsigned short* Ab, const unsigned short* Bb,
                                           uint32_t sA, uint32_t sB, int kb, int tid) {
#pragma unroll
    for (int i = 0; i < 4; i++) {
        int u = tid + 256 * i, r = u >> 3, c = u & 7;
        int off = r * 128 + c * 16; off ^= (off >> 3) & 0x70;
        cp16(sA + off, Ab + (size_t)r * KP + kb + c * 8);
    }
#pragma unroll
    for (int i = 0; i < 4; i++) {
        int u = tid + 256 * i, r = u >> 3, c = u & 7;
        int off = r * 128 + c * 16; off ^= (off >> 3) & 0x70;
        cp16(sB + off, Bb + (size_t)r * KP + kb + c * 8);
    }
}

__device__ __forceinline__ void gemm_tile(const unsigned short* Ab, const unsigned short* Bb,
                                          uint32_t smb, int tid, float acc[2][8][4]) {
    const int lane = tid & 31, w = tid >> 5;
    const int wr = w >> 1, wc = w & 1;
#pragma unroll
    for (int mi = 0; mi < 2; mi++)
#pragma unroll
        for (int ni = 0; ni < 8; ni++)
#pragma unroll
            for (int d = 0; d < 4; d++) acc[mi][ni][d] = 0.f;

    // per-thread ldmatrix base addresses (within a 16KB tile)
    const int la = lane & 15, ka = (lane >> 4) * 16;
    uint32_t pA[2]; int xa[2];
#pragma unroll
    for (int mi = 0; mi < 2; mi++) {
        int row = wr * 32 + mi * 16 + la;
        pA[mi] = row * 128; xa[mi] = (row & 7) << 4;
    }
    const int lb = (lane & 7) + ((lane >> 4) & 1) * 8, kbB = ((lane >> 3) & 1) * 16;
    uint32_t pB[4]; int xb[4];
#pragma unroll
    for (int g = 0; g < 4; g++) {
        int row = wc * 64 + g * 16 + lb;
        pB[g] = row * 128; xb[g] = (row & 7) << 4;
    }

    load_stage(Ab, Bb, smb, smb + TILE_BYTES, 0, tid);
    CP_COMMIT();
    for (int s = 0; s < NSTAGE; ++s) {
        const int buf = s & 1;
        if (s + 1 < NSTAGE) {
            const int nbuf = (s + 1) & 1;
            load_stage(Ab, Bb, smb + nbuf * 2 * TILE_BYTES,
                       smb + nbuf * 2 * TILE_BYTES + TILE_BYTES, (s + 1) * 64, tid);
        }
        CP_COMMIT();
        CP_WAIT1();
        __syncthreads();
        const uint32_t sA = smb + buf * 2 * TILE_BYTES;
        const uint32_t sB = sA + TILE_BYTES;
#pragma unroll
        for (int kk = 0; kk < 4; kk++) {
            const int kb = kk * 32;
            uint32_t a[2][4], bf[4][4];
#pragma unroll
            for (int mi = 0; mi < 2; mi++)
                ldm_x4(sA + pA[mi] + ((kb + ka) ^ xa[mi]),
                       a[mi][0], a[mi][1], a[mi][2], a[mi][3]);
#pragma unroll
            for (int g = 0; g < 4; g++)
                ldm_x4(sB + pB[g] + ((kb + kbB) ^ xb[g]),
                       bf[g][0], bf[g][1], bf[g][2], bf[g][3]);
#pragma unroll
            for (int mi = 0; mi < 2; mi++)
#pragma unroll
                for (int ni = 0; ni < 8; ni++) {
                    const int g = ni >> 1, p = ni & 1;
                    mma16816(acc[mi][ni], a[mi], bf[g][p * 2], bf[g][p * 2 + 1]);
                }
        }
        __syncthreads();
    }
}

// ---------------- K3: scores GEMM + fused argmax ----------------
__global__ __launch_bounds__(256, 1) void k_scores_mma() {
    extern __shared__ char smx[];
    const int n0 = blockIdx.x * 128, m0 = blockIdx.y * 128, b = blockIdx.z;
    const int tid = threadIdx.x, lane = tid & 31, w = tid >> 5;
    const int wr = w >> 1, wc = w & 1;
    float acc[2][8][4];
    gemm_tile(g_S + ((size_t)(b * T2 + m0)) * KP,
              g_Dm + ((size_t)(b * T2 + n0)) * KP, smem_u32(smx), tid, acc);
#pragma unroll
    for (int mi = 0; mi < 2; mi++) {
#pragma unroll
        for (int hi = 0; hi < 2; hi++) {
            float best = -FLT_MAX; int bcol = 0;
#pragma unroll
            for (int ni = 0; ni < 8; ni++) {
#pragma unroll
                for (int d = 0; d < 2; d++) {
                    float v = acc[mi][ni][hi * 2 + d];
                    int c = n0 + wc * 64 + ni * 8 + 2 * (lane & 3) + d;
                    if (v > best) { best = v; bcol = c; }
                }
            }
            unsigned u = __float_as_uint(best);
            u = (u & 0x80000000u) ? ~u : (u | 0x80000000u);
            unsigned long long key = ((unsigned long long)u << 32) | (unsigned)(2047 - bcol);
#pragma unroll
            for (int o = 1; o <= 2; o <<= 1) {
                unsigned long long ok = __shfl_xor_sync(0xFFFFFFFFu, key, o);
                if (ok > key) key = ok;
            }
            if ((lane & 3) == 0) {
                int row = m0 + wr * 32 + mi * 16 + (lane >> 2) + hi * 8;
                atomicMax(&g_key[b * T2 + row], key);
            }
        }
    }
}

// ---------------- K4: bitonic top-k ----------------
__global__ void k_topk() {
    const int b = blockIdx.x;
    __shared__ unsigned long long keys[T2];
    const int tid = threadIdx.x;
    g_winner[b * T2 + tid] = -1;
    g_winner[b * T2 + tid + 1024] = -1;
    for (int t = tid; t < Tn; t += 1024) g_merged[b * Tn + t] = 0;
    for (int i = tid; i < T2; i += 1024) {
        unsigned long long kv = g_key[b * T2 + i];
        unsigned mono = (unsigned)(kv >> 32);
        g_barg[b * T2 + i] = 2047 - (int)(kv & 0xFFFFFFFFu);
        keys[i] = ((unsigned long long)(~mono) << 32) | (unsigned)i;
    }
    __syncthreads();
    for (int k2 = 2; k2 <= T2; k2 <<= 1) {
        for (int j = k2 >> 1; j > 0; j >>= 1) {
            for (int i = tid; i < T2; i += 1024) {
                int ixj = i ^ j;
                if (ixj > i) {
                    bool up = ((i & k2) == 0);
                    unsigned long long a = keys[i], c = keys[ixj];
                    if ((a > c) == up) { keys[i] = c; keys[ixj] = a; }
                }
            }
            __syncthreads();
        }
    }
    if (tid < Rn) {
        int s = (int)(keys[tid] & 0xFFFFFFFFu);
        int stok = 2 * s + 1;
        int dloc = g_barg[b * T2 + s];
        g_srctok[b * Rn + tid] = stok;
        g_dsttok[b * Rn + tid] = 2 * dloc;
        g_merged[b * Tn + stok] = 1;
        atomicMax(&g_winner[b * T2 + dloc], tid);
    }
}

// ---------------- K5: compaction ----------------
__global__ void k_scan() {
    const int b = blockIdx.x;
    __shared__ int sums[1024];
    const int tid = threadIdx.x;
    const int base = tid * 4;
    int loc[4]; int c0 = 0;
#pragma unroll
    for (int i = 0; i < 4; i++) { loc[i] = g_merged[b * Tn + base + i] ? 0 : 1; c0 += loc[i]; }
    sums[tid] = c0; __syncthreads();
    for (int off = 1; off < 1024; off <<= 1) {
        int v = (tid >= off) ? sums[tid - off] : 0;
        __syncthreads();
        sums[tid] += v;
        __syncthreads();
    }
    int run = (tid == 0) ? 0 : sums[tid - 1];
#pragma unroll
    for (int i = 0; i < 4; i++)
        if (loc[i]) { g_col[b * Cn + run] = base + i; run++; }
}

// ---------------- K6: merged matrix, fp16 split ----------------
__global__ void k_build2(const float* __restrict__ x) {
    const int b = blockIdx.y, c = blockIdx.x;
    const int t = g_col[b * Cn + c];
    const int tid = threadIdx.x; // 128
    const float* xb = x + (size_t)b * Tn * Dn;
    float4 v = *(const float4*)(xb + (size_t)t * Dn + tid * 4);
    if ((t & 1) == 0) {
        int w = g_winner[b * T2 + (t >> 1)];
        if (w >= 0) {
            int mt = g_srctok[b * Rn + w];
            float4 u = *(const float4*)(xb + (size_t)mt * Dn + tid * 4);
            v.x = (u.x + v.x) * 0.5f; v.y = (u.y + v.y) * 0.5f;
            v.z = (u.z + v.z) * 0.5f; v.w = (u.w + v.w) * 0.5f;
        }
    }
    unsigned short* rp = g_A2 + ((size_t)(b * Cn + c)) * KP;
    float a[4] = {v.x, v.y, v.z, v.w};
    unsigned short hs[4], ms[4];
#pragma unroll
    for (int j = 0; j < 4; j++) {
        __half hh = __float2half_rn(a[j]);
        hs[j] = __half_as_ushort(hh);
        ms[j] = __half_as_ushort(__float2half_rn(a[j] - __half2float(hh)));
    }
    ushort4 h4 = make_ushort4(hs[0], hs[1], hs[2], hs[3]);
    ushort4 m4 = make_ushort4(ms[0], ms[1], ms[2], ms[3]);
    int k0 = tid * 4;
    *(ushort4*)(rp + k0)        = h4;
    *(ushort4*)(rp + 512 + k0)  = h4;
    *(ushort4*)(rp + 1024 + k0) = m4;
}

// ---------------- K7: hidden GEMM + scattered epilogue ----------------
__global__ __launch_bounds__(256, 1) void k_hidden_mma(const float* __restrict__ bias,
                                                       float* __restrict__ out) {
    extern __shared__ char smx[];
    const int n0 = blockIdx.x * 128, m0 = blockIdx.y * 128;
    const int b = m0 / Cn, cm0 = m0 % Cn;
    const int tid = threadIdx.x, lane = tid & 31, w = tid >> 5;
    const int wr = w >> 1, wc = w & 1;
    int*   s_tok  = (int*)(smx + SMEM_MAIN);
    float* s_bias = (float*)(smx + SMEM_MAIN + 512);
    if (tid < 128) {
        s_tok[tid]  = g_col[b * Cn + cm0 + tid];
        s_bias[tid] = bias[n0 + tid];
    }
    __syncthreads();
    float acc[2][8][4];
    gemm_tile(g_A2 + (size_t)m0 * KP, g_Wt + (size_t)n0 * KP, smem_u32(smx), tid, acc);
#pragma unroll
    for (int mi = 0; mi < 2; mi++) {
#pragma unroll
        for (int hi = 0; hi < 2; hi++) {
            int row = wr * 32 + mi * 16 + (lane >> 2) + hi * 8;
            int tok = s_tok[row];
            float* op = out + (size_t)b * Tn * Dn + (size_t)tok * Dn + n0;
#pragma unroll
            for (int ni = 0; ni < 8; ni++) {
                int col = wc * 64 + ni * 8 + 2 * (lane & 3);
                float2 o;
                o.x = acc[mi][ni][hi * 2 + 0] + s_bias[col + 0];
                o.y = acc[mi][ni][hi * 2 + 1] + s_bias[col + 1];
                *(float2*)(op + col) = o;
            }
        }
    }
}

// ---------------- K8: out[src] = out[dst] ----------------
__global__ void k_copy(float* __restrict__ out) {
    const int b = blockIdx.y, i = blockIdx.x;
    const int st = g_srctok[b * Rn + i], dt = g_dsttok[b * Rn + i];
    const int tid = threadIdx.x; // 128
    const float4* src = (const float4*)(out + (size_t)b * Tn * Dn + (size_t)dt * Dn);
    float4* dst = (float4*)(out + (size_t)b * Tn * Dn + (size_t)st * Dn);
    dst[tid] = src[tid];
}

extern "C" void kernel_launch(void* const* d_in, const int* in_sizes, int n_in,
                              void* d_out, int out_size) {
    const float* x    = (const float*)d_in[0];
    const float* W    = (const float*)d_in[1];
    const float* bias = (const float*)d_in[2];
    float* out = (float*)d_out;

    static int cfg = 0;
    if (!cfg) {
        cudaFuncSetAttribute(k_scores_mma, cudaFuncAttributeMaxDynamicSharedMemorySize, SMEM_DYN);
        cudaFuncSetAttribute(k_hidden_mma, cudaFuncAttributeMaxDynamicSharedMemorySize, SMEM_DYN);
        cfg = 1;
    }

    k_prep<<<Bn * Tn / 8, 256>>>(x);
    k_wprep<<<Dn, 256>>>(W);
    k_scores_mma<<<dim3(T2 / 128, T2 / 128, Bn), 256, SMEM_DYN>>>();
    k_topk<<<Bn, 1024>>>();
    k_scan<<<Bn, 1024>>>();
    k_build2<<<dim3(Cn, Bn), 128>>>(x);
    k_hidden_mma<<<dim3(Dn / 128, (Bn * Cn) / 128), 256, SMEM_DYN>>>(bias, out);
    k_copy<<<dim3(Rn, Bn), 128>>>(out);
}

// round 6
// speedup vs baseline: 4.7234x; 1.3441x over previous
#include <cuda_runtime.h>
#include <cuda_fp16.h>
#include <cstdint>
#include <float.h>
#include <math.h>

#define Bn 8
#define Tn 4096
#define Dn 512
#define Rn 1024
#define T2 2048
#define Cn 3072
#define KP 1536                    // hidden GEMM augmented K
#define BM 256
#define BN 128
#define A_BYTES (BM * 128)         // 32768
#define B_BYTES (BN * 128)         // 16384
#define STG_BYTES (A_BYTES + B_BYTES)
#define SMEM_DYN (3 * STG_BYTES + 2048)

// ---------------- device scratch ----------------
__device__ __align__(16) unsigned short g_S [(size_t)Bn * T2 * 512];  // src hi fp16
__device__ __align__(16) unsigned short g_Dm[(size_t)Bn * T2 * 512];  // dst hi fp16
__device__ __align__(16) unsigned short g_A2[(size_t)Bn * Cn * KP];   // merged aug [H,H,M]
__device__ __align__(16) unsigned short g_Wt[(size_t)Dn * KP];        // W^T aug [H,M,H]
__device__ float g_SC[(size_t)Bn * T2 * T2];                          // approx scores (134MB)
__device__ unsigned g_rmax[Bn * T2];
__device__ float g_inv[Bn * Tn];
__device__ unsigned long long g_key[Bn * T2];
__device__ int   g_barg[Bn * T2];
__device__ int   g_srctok[Bn * Rn];
__device__ int   g_dsttok[Bn * Rn];
__device__ int   g_winner[Bn * T2];
__device__ unsigned char g_merged[Bn * Tn];
__device__ int   g_col[Bn * Cn];

// ---------------- helpers ----------------
__device__ __forceinline__ uint32_t smem_u32(const void* p) {
    uint32_t a;
    asm("{ .reg .u64 t; cvta.to.shared.u64 t, %1; cvt.u32.u64 %0, t; }" : "=r"(a) : "l"(p));
    return a;
}
__device__ __forceinline__ void cp16(uint32_t dst, const void* src) {
    asm volatile("cp.async.cg.shared.global [%0], [%1], 16;\n" :: "r"(dst), "l"(src));
}
#define CP_COMMIT() asm volatile("cp.async.commit_group;\n" ::: "memory")
#define CP_WAIT1()  asm volatile("cp.async.wait_group 1;\n" ::: "memory")
__device__ __forceinline__ void ldm_x4(uint32_t a, uint32_t& r0, uint32_t& r1,
                                       uint32_t& r2, uint32_t& r3) {
    asm volatile("ldmatrix.sync.aligned.m8n8.x4.shared.b16 {%0,%1,%2,%3}, [%4];\n"
        : "=r"(r0), "=r"(r1), "=r"(r2), "=r"(r3) : "r"(a));
}
__device__ __forceinline__ void mma16816(float* c, const uint32_t* a, uint32_t b0, uint32_t b1) {
    asm volatile("mma.sync.aligned.m16n8k16.row.col.f32.f16.f16.f32 "
        "{%0,%1,%2,%3}, {%4,%5,%6,%7}, {%8,%9}, {%0,%1,%2,%3};\n"
        : "+f"(c[0]), "+f"(c[1]), "+f"(c[2]), "+f"(c[3])
        : "r"(a[0]), "r"(a[1]), "r"(a[2]), "r"(a[3]), "r"(b0), "r"(b1));
}

// ---------------- K1: norms + hi-only fp16 of normalized rows ----------------
__global__ void k_prep(const float* __restrict__ x) {
    int row = blockIdx.x * 8 + (threadIdx.x >> 5);
    int lane = threadIdx.x & 31;
    int b = row >> 12, t = row & 4095;
    const float4* p = (const float4*)(x + (size_t)row * Dn);
    float4 v[4]; float ss = 0.f;
#pragma unroll
    for (int i = 0; i < 4; i++) {
        v[i] = p[lane + 32 * i];
        ss += v[i].x * v[i].x + v[i].y * v[i].y + v[i].z * v[i].z + v[i].w * v[i].w;
    }
#pragma unroll
    for (int o = 16; o; o >>= 1) ss += __shfl_xor_sync(0xFFFFFFFFu, ss, o);
    float inv = 1.0f / fmaxf(sqrtf(ss), 1e-12f);
    float sc = 1024.0f * inv;
    if (lane == 0) g_inv[row] = inv;
    int odd = t & 1, s = t >> 1;
    unsigned short* rp = (odd ? g_S : g_Dm) + ((size_t)(b * T2 + s)) * 512;
    if (odd && lane == 0) g_rmax[b * T2 + s] = 0u;
#pragma unroll
    for (int i = 0; i < 4; i++) {
        int k0 = 4 * (lane + 32 * i);
        float a[4] = {v[i].x * sc, v[i].y * sc, v[i].z * sc, v[i].w * sc};
        unsigned short hs[4];
#pragma unroll
        for (int j = 0; j < 4; j++) hs[j] = __half_as_ushort(__float2half_rn(a[j]));
        *(ushort4*)(rp + k0) = make_ushort4(hs[0], hs[1], hs[2], hs[3]);
    }
}

// ---------------- K2: W^T aug split ----------------
__global__ void k_wprep(const float* __restrict__ W) {
    int n = blockIdx.x;
    for (int k = threadIdx.x; k < Dn; k += 256) {
        float w = W[(size_t)k * Dn + n];
        __half hh = __float2half_rn(w);
        unsigned short h = __half_as_ushort(hh);
        unsigned short m = __half_as_ushort(__float2half_rn(w - __half2float(hh)));
        size_t base = (size_t)n * KP;
        g_Wt[base + k] = h; g_Wt[base + 512 + k] = m; g_Wt[base + 1024 + k] = h;
    }
}

// ---------------- HMMA engine: C[256x128] = A[256xKA] * B[128xKA]^T, 512 thr ----------------
__device__ __forceinline__ void load_stage2(const unsigned short* Ab, const unsigned short* Bb,
                                            int KA, uint32_t sA, uint32_t sB, int kb, int tid) {
#pragma unroll
    for (int i = 0; i < 4; i++) {
        int u = tid + 512 * i, r = u >> 3, c = u & 7;
        int off = r * 128 + c * 16; off ^= (off >> 3) & 0x70;
        cp16(sA + off, Ab + (size_t)r * KA + kb + c * 8);
    }
#pragma unroll
    for (int i = 0; i < 2; i++) {
        int u = tid + 512 * i, r = u >> 3, c = u & 7;
        int off = r * 128 + c * 16; off ^= (off >> 3) & 0x70;
        cp16(sB + off, Bb + (size_t)r * KA + kb + c * 8);
    }
}

template<int NST>
__device__ __forceinline__ void gemm_tile(const unsigned short* Ab, const unsigned short* Bb,
                                          int KA, uint32_t smb, int tid, float acc[2][8][4]) {
    const int lane = tid & 31, w = tid >> 5;
    const int wr = w >> 1, wc = w & 1;
#pragma unroll
    for (int mi = 0; mi < 2; mi++)
#pragma unroll
        for (int ni = 0; ni < 8; ni++)
#pragma unroll
            for (int d = 0; d < 4; d++) acc[mi][ni][d] = 0.f;

    const int la = lane & 15, ka = (lane >> 4) * 16;
    uint32_t pA[2]; int xa[2];
#pragma unroll
    for (int mi = 0; mi < 2; mi++) {
        int row = wr * 32 + mi * 16 + la;
        pA[mi] = row * 128; xa[mi] = (row & 7) << 4;
    }
    const int lb = (lane & 7) + ((lane >> 4) & 1) * 8, kbB = ((lane >> 3) & 1) * 16;
    uint32_t pB[4]; int xb[4];
#pragma unroll
    for (int g = 0; g < 4; g++) {
        int row = wc * 64 + g * 16 + lb;
        pB[g] = row * 128; xb[g] = (row & 7) << 4;
    }

    load_stage2(Ab, Bb, KA, smb, smb + A_BYTES, 0, tid);
    CP_COMMIT();
    load_stage2(Ab, Bb, KA, smb + STG_BYTES, smb + STG_BYTES + A_BYTES, 64, tid);
    CP_COMMIT();
    for (int s = 0; s < NST; ++s) {
        CP_WAIT1();
        __syncthreads();
        if (s + 2 < NST) {
            int nb = (s + 2) % 3;
            load_stage2(Ab, Bb, KA, smb + nb * STG_BYTES,
                        smb + nb * STG_BYTES + A_BYTES, (s + 2) * 64, tid);
        }
        CP_COMMIT();
        const uint32_t sA = smb + (s % 3) * STG_BYTES;
        const uint32_t sB = sA + A_BYTES;
#pragma unroll
        for (int kk = 0; kk < 4; kk++) {
            const int kb = kk * 32;
            uint32_t a[2][4], bf[4][4];
#pragma unroll
            for (int mi = 0; mi < 2; mi++)
                ldm_x4(sA + pA[mi] + ((kb + ka) ^ xa[mi]),
                       a[mi][0], a[mi][1], a[mi][2], a[mi][3]);
#pragma unroll
            for (int g = 0; g < 4; g++)
                ldm_x4(sB + pB[g] + ((kb + kbB) ^ xb[g]),
                       bf[g][0], bf[g][1], bf[g][2], bf[g][3]);
#pragma unroll
            for (int mi = 0; mi < 2; mi++)
#pragma unroll
                for (int ni = 0; ni < 8; ni++) {
                    const int g = ni >> 1, p = ni & 1;
                    mma16816(acc[mi][ni], a[mi], bf[g][p * 2], bf[g][p * 2 + 1]);
                }
        }
    }
}

// ---------------- K3a: hi-only scores GEMM -> g_SC + per-row approx max ----------------
__global__ __launch_bounds__(512, 1) void k_scores_hi() {
    extern __shared__ char smx[];
    const int n0 = blockIdx.x * BN, m0 = blockIdx.y * BM, b = blockIdx.z;
    const int tid = threadIdx.x, lane = tid & 31, w = tid >> 5;
    const int wr = w >> 1, wc = w & 1;
    float acc[2][8][4];
    gemm_tile<8>(g_S + ((size_t)(b * T2 + m0)) * 512,
                 g_Dm + ((size_t)(b * T2 + n0)) * 512, 512, smem_u32(smx), tid, acc);
#pragma unroll
    for (int mi = 0; mi < 2; mi++) {
#pragma unroll
        for (int hi = 0; hi < 2; hi++) {
            int row = m0 + wr * 32 + mi * 16 + (lane >> 2) + hi * 8;
            float* SCr = g_SC + ((size_t)(b * T2) + row) * T2 + n0 + wc * 64 + 2 * (lane & 3);
            float rmax = -FLT_MAX;
#pragma unroll
            for (int ni = 0; ni < 8; ni++) {
                float v0 = acc[mi][ni][hi * 2], v1 = acc[mi][ni][hi * 2 + 1];
                rmax = fmaxf(rmax, fmaxf(v0, v1));
                *(float2*)(SCr + ni * 8) = make_float2(v0, v1);
            }
#pragma unroll
            for (int o = 1; o <= 2; o <<= 1)
                rmax = fmaxf(rmax, __shfl_xor_sync(0xFFFFFFFFu, rmax, o));
            if ((lane & 3) == 0) {
                unsigned u = __float_as_uint(rmax);
                u = (u & 0x80000000u) ? ~u : (u | 0x80000000u);
                atomicMax(&g_rmax[b * T2 + row], u);
            }
        }
    }
}

// ---------------- K3b: exact candidate rescore (1 warp / src row) ----------------
__global__ void k_cand(const float* __restrict__ x) {
    const int b = blockIdx.y;
    const int m = blockIdx.x * 8 + (threadIdx.x >> 5);
    const int lane = threadIdx.x & 31;
    const float* SC = g_SC + ((size_t)(b * T2) + m) * T2;
    unsigned rm = g_rmax[b * T2 + m];
    float rmax = __uint_as_float((rm & 0x80000000u) ? (rm & 0x7FFFFFFFu) : ~rm);
    float thr = rmax - 1100.0f;   // 1e-3 in correlation units (scale 2^20)
    const float* xb = x + (size_t)b * Tn * Dn;
    const float* xs = xb + (size_t)(2 * m + 1) * Dn;
    const float inv_s = g_inv[b * Tn + 2 * m + 1];
    float best = -FLT_MAX; int bcol = 0x7FFFFFFF;
    for (int c0 = 0; c0 < T2; c0 += 32) {
        float sv = SC[c0 + lane];
        unsigned msk = __ballot_sync(0xFFFFFFFFu, sv >= thr);
        while (msk) {
            int j = c0 + __ffs(msk) - 1; msk &= msk - 1;
            const float* xd = xb + (size_t)(2 * j) * Dn;
            float acc = 0.f;
#pragma unroll
            for (int i = 0; i < 4; i++) {
                int k = lane * 4 + i * 128;
                float4 a = *(const float4*)(xs + k);
                float4 d = *(const float4*)(xd + k);
                acc += a.x * d.x + a.y * d.y + a.z * d.z + a.w * d.w;
            }
#pragma unroll
            for (int o = 16; o; o >>= 1) acc += __shfl_xor_sync(0xFFFFFFFFu, acc, o);
            float e = acc * inv_s * g_inv[b * Tn + 2 * j];
            if (e > best || (e == best && j < bcol)) { best = e; bcol = j; }
        }
    }
    if (lane == 0) {
        unsigned u = __float_as_uint(best);
        u = (u & 0x80000000u) ? ~u : (u | 0x80000000u);
        g_key[b * T2 + m] = ((unsigned long long)u << 32) | (unsigned)(2047 - bcol);
    }
}

// ---------------- K4: bitonic top-k ----------------
__global__ void k_topk() {
    const int b = blockIdx.x;
    __shared__ unsigned long long keys[T2];
    const int tid = threadIdx.x;
    g_winner[b * T2 + tid] = -1;
    g_winner[b * T2 + tid + 1024] = -1;
    for (int t = tid; t < Tn; t += 1024) g_merged[b * Tn + t] = 0;
    for (int i = tid; i < T2; i += 1024) {
        unsigned long long kv = g_key[b * T2 + i];
        unsigned mono = (unsigned)(kv >> 32);
        g_barg[b * T2 + i] = 2047 - (int)(kv & 0xFFFFFFFFu);
        keys[i] = ((unsigned long long)(~mono) << 32) | (unsigned)i;
    }
    __syncthreads();
    for (int k2 = 2; k2 <= T2; k2 <<= 1) {
        for (int j = k2 >> 1; j > 0; j >>= 1) {
            for (int i = tid; i < T2; i += 1024) {
                int ixj = i ^ j;
                if (ixj > i) {
                    bool up = ((i & k2) == 0);
                    unsigned long long a = keys[i], c = keys[ixj];
                    if ((a > c) == up) { keys[i] = c; keys[ixj] = a; }
                }
            }
            __syncthreads();
        }
    }
    if (tid < Rn) {
        int s = (int)(keys[tid] & 0xFFFFFFFFu);
        int stok = 2 * s + 1;
        int dloc = g_barg[b * T2 + s];
        g_srctok[b * Rn + tid] = stok;
        g_dsttok[b * Rn + tid] = 2 * dloc;
        g_merged[b * Tn + stok] = 1;
        atomicMax(&g_winner[b * T2 + dloc], tid);
    }
}

// ---------------- K5: compaction ----------------
__global__ void k_scan() {
    const int b = blockIdx.x;
    __shared__ int sums[1024];
    const int tid = threadIdx.x;
    const int base = tid * 4;
    int loc[4]; int c0 = 0;
#pragma unroll
    for (int i = 0; i < 4; i++) { loc[i] = g_merged[b * Tn + base + i] ? 0 : 1; c0 += loc[i]; }
    sums[tid] = c0; __syncthreads();
    for (int off = 1; off < 1024; off <<= 1) {
        int v = (tid >= off) ? sums[tid - off] : 0;
        __syncthreads();
        sums[tid] += v;
        __syncthreads();
    }
    int run = (tid == 0) ? 0 : sums[tid - 1];
#pragma unroll
    for (int i = 0; i < 4; i++)
        if (loc[i]) { g_col[b * Cn + run] = base + i; run++; }
}

// ---------------- K6: merged matrix, fp16 3-term split ----------------
__global__ void k_build2(const float* __restrict__ x) {
    const int b = blockIdx.y, c = blockIdx.x;
    const int t = g_col[b * Cn + c];
    const int tid = threadIdx.x; // 128
    const float* xb = x + (size_t)b * Tn * Dn;
    float4 v = *(const float4*)(xb + (size_t)t * Dn + tid * 4);
    if ((t & 1) == 0) {
        int w = g_winner[b * T2 + (t >> 1)];
        if (w >= 0) {
            int mt = g_srctok[b * Rn + w];
            float4 u = *(const float4*)(xb + (size_t)mt * Dn + tid * 4);
            v.x = (u.x + v.x) * 0.5f; v.y = (u.y + v.y) * 0.5f;
            v.z = (u.z + v.z) * 0.5f; v.w = (u.w + v.w) * 0.5f;
        }
    }
    unsigned short* rp = g_A2 + ((size_t)(b * Cn + c)) * KP;
    float a[4] = {v.x, v.y, v.z, v.w};
    unsigned short hs[4], ms[4];
#pragma unroll
    for (int j = 0; j < 4; j++) {
        __half hh = __float2half_rn(a[j]);
        hs[j] = __half_as_ushort(hh);
        ms[j] = __half_as_ushort(__float2half_rn(a[j] - __half2float(hh)));
    }
    ushort4 h4 = make_ushort4(hs[0], hs[1], hs[2], hs[3]);
    ushort4 m4 = make_ushort4(ms[0], ms[1], ms[2], ms[3]);
    int k0 = tid * 4;
    *(ushort4*)(rp + k0)        = h4;
    *(ushort4*)(rp + 512 + k0)  = h4;
    *(ushort4*)(rp + 1024 + k0) = m4;
}

// ---------------- K7: hidden GEMM + scattered epilogue ----------------
__global__ __launch_bounds__(512, 1) void k_hidden_mma(const float* __restrict__ bias,
                                                       float* __restrict__ out) {
    extern __shared__ char smx[];
    const int n0 = blockIdx.x * BN, m0 = blockIdx.y * BM;
    const int b = m0 / Cn, cm0 = m0 % Cn;
    const int tid = threadIdx.x, lane = tid & 31, w = tid >> 5;
    const int wr = w >> 1, wc = w & 1;
    int*   s_tok  = (int*)(smx + 3 * STG_BYTES);
    float* s_bias = (float*)(smx + 3 * STG_BYTES + 1024);
    if (tid < 256) s_tok[tid] = g_col[b * Cn + cm0 + tid];
    if (tid >= 256 && tid < 384) s_bias[tid - 256] = bias[n0 + tid - 256];
    __syncthreads();
    float acc[2][8][4];
    gemm_tile<24>(g_A2 + (size_t)m0 * KP, g_Wt + (size_t)n0 * KP, KP, smem_u32(smx), tid, acc);
#pragma unroll
    for (int mi = 0; mi < 2; mi++) {
#pragma unroll
        for (int hi = 0; hi < 2; hi++) {
            int row = wr * 32 + mi * 16 + (lane >> 2) + hi * 8;
            int tok = s_tok[row];
            float* op = out + (size_t)b * Tn * Dn + (size_t)tok * Dn + n0;
#pragma unroll
            for (int ni = 0; ni < 8; ni++) {
                int col = wc * 64 + ni * 8 + 2 * (lane & 3);
                float2 o;
                o.x = acc[mi][ni][hi * 2 + 0] + s_bias[col + 0];
                o.y = acc[mi][ni][hi * 2 + 1] + s_bias[col + 1];
                *(float2*)(op + col) = o;
            }
        }
    }
}

// ---------------- K8: out[src] = out[dst] ----------------
__global__ void k_copy(float* __restrict__ out) {
    const int b = blockIdx.y, i = blockIdx.x;
    const int st = g_srctok[b * Rn + i], dt = g_dsttok[b * Rn + i];
    const int tid = threadIdx.x; // 128
    const float4* src = (const float4*)(out + (size_t)b * Tn * Dn + (size_t)dt * Dn);
    float4* dst = (float4*)(out + (size_t)b * Tn * Dn + (size_t)st * Dn);
    dst[tid] = src[tid];
}

extern "C" void kernel_launch(void* const* d_in, const int* in_sizes, int n_in,
                              void* d_out, int out_size) {
    const float* x    = (const float*)d_in[0];
    const float* W    = (const float*)d_in[1];
    const float* bias = (const float*)d_in[2];
    float* out = (float*)d_out;

    static int cfg = 0;
    if (!cfg) {
        cudaFuncSetAttribute(k_scores_hi, cudaFuncAttributeMaxDynamicSharedMemorySize, SMEM_DYN);
        cudaFuncSetAttribute(k_hidden_mma, cudaFuncAttributeMaxDynamicSharedMemorySize, SMEM_DYN);
        cfg = 1;
    }

    k_prep<<<Bn * Tn / 8, 256>>>(x);
    k_wprep<<<Dn, 256>>>(W);
    k_scores_hi<<<dim3(T2 / BN, T2 / BM, Bn), 512, SMEM_DYN>>>();
    k_cand<<<dim3(T2 / 8, Bn), 256>>>(x);
    k_topk<<<Bn, 1024>>>();
    k_scan<<<Bn, 1024>>>();
    k_build2<<<dim3(Cn, Bn), 128>>>(x);
    k_hidden_mma<<<dim3(Dn / BN, (Bn * Cn) / BM), 512, SMEM_DYN>>>(bias, out);
    k_copy<<<dim3(Rn, Bn), 128>>>(out);
}

// round 7
// speedup vs baseline: 5.9283x; 1.2551x over previous
#include <cuda_runtime.h>
#include <cuda_fp16.h>
#include <cstdint>
#include <float.h>
#include <math.h>

#define Bn 8
#define Tn 4096
#define Dn 512
#define Rn 1024
#define T2 2048
#define Cn 3072
#define KP 1536                    // hidden GEMM augmented K
#define BM 256
#define BN 128
#define A_BYTES (BM * 128)
#define B_BYTES (BN * 128)
#define STG_BYTES (A_BYTES + B_BYTES)
#define SMEM_DYN (3 * STG_BYTES + 2048)
#define CAND_CAP 160

// ---------------- device scratch ----------------
__device__ __align__(16) unsigned short g_S [(size_t)Bn * T2 * 512];  // src hi fp16 (scale 32)
__device__ __align__(16) unsigned short g_Dm[(size_t)Bn * T2 * 512];  // dst hi fp16 (scale 32)
__device__ __align__(16) unsigned short g_A2[(size_t)Bn * Cn * KP];   // merged aug [H,H,M]
__device__ __align__(16) unsigned short g_Wt[(size_t)Dn * KP];        // W^T aug [H,M,H]
__device__ __align__(16) __half g_SCh[(size_t)Bn * T2 * T2];          // approx scores fp16 (67MB)
__device__ unsigned g_rmax[Bn * T2];
__device__ float g_inv[Bn * Tn];
__device__ unsigned long long g_key[Bn * T2];
__device__ int   g_barg[Bn * T2];
__device__ int   g_srctok[Bn * Rn];
__device__ int   g_dsttok[Bn * Rn];
__device__ int   g_winner[Bn * T2];
__device__ unsigned char g_merged[Bn * Tn];
__device__ int   g_col[Bn * Cn];

// ---------------- helpers ----------------
__device__ __forceinline__ uint32_t smem_u32(const void* p) {
    uint32_t a;
    asm("{ .reg .u64 t; cvta.to.shared.u64 t, %1; cvt.u32.u64 %0, t; }" : "=r"(a) : "l"(p));
    return a;
}
__device__ __forceinline__ void cp16(uint32_t dst, const void* src) {
    asm volatile("cp.async.cg.shared.global [%0], [%1], 16;\n" :: "r"(dst), "l"(src));
}
#define CP_COMMIT() asm volatile("cp.async.commit_group;\n" ::: "memory")
#define CP_WAIT1()  asm volatile("cp.async.wait_group 1;\n" ::: "memory")
__device__ __forceinline__ void ldm_x4(uint32_t a, uint32_t& r0, uint32_t& r1,
                                       uint32_t& r2, uint32_t& r3) {
    asm volatile("ldmatrix.sync.aligned.m8n8.x4.shared.b16 {%0,%1,%2,%3}, [%4];\n"
        : "=r"(r0), "=r"(r1), "=r"(r2), "=r"(r3) : "r"(a));
}
__device__ __forceinline__ void mma16816(float* c, const uint32_t* a, uint32_t b0, uint32_t b1) {
    asm volatile("mma.sync.aligned.m16n8k16.row.col.f32.f16.f16.f32 "
        "{%0,%1,%2,%3}, {%4,%5,%6,%7}, {%8,%9}, {%0,%1,%2,%3};\n"
        : "+f"(c[0]), "+f"(c[1]), "+f"(c[2]), "+f"(c[3])
        : "r"(a[0]), "r"(a[1]), "r"(a[2]), "r"(a[3]), "r"(b0), "r"(b1));
}

// ---------------- K1: norms + hi-only fp16 of normalized rows (scale 32) ----------------
__global__ void k_prep(const float* __restrict__ x) {
    int row = blockIdx.x * 8 + (threadIdx.x >> 5);
    int lane = threadIdx.x & 31;
    int b = row >> 12, t = row & 4095;
    const float4* p = (const float4*)(x + (size_t)row * Dn);
    float4 v[4]; float ss = 0.f;
#pragma unroll
    for (int i = 0; i < 4; i++) {
        v[i] = p[lane + 32 * i];
        ss += v[i].x * v[i].x + v[i].y * v[i].y + v[i].z * v[i].z + v[i].w * v[i].w;
    }
#pragma unroll
    for (int o = 16; o; o >>= 1) ss += __shfl_xor_sync(0xFFFFFFFFu, ss, o);
    float inv = 1.0f / fmaxf(sqrtf(ss), 1e-12f);
    float sc = 32.0f * inv;
    if (lane == 0) g_inv[row] = inv;
    int odd = t & 1, s = t >> 1;
    unsigned short* rp = (odd ? g_S : g_Dm) + ((size_t)(b * T2 + s)) * 512;
    if (odd && lane == 0) g_rmax[b * T2 + s] = 0u;
#pragma unroll
    for (int i = 0; i < 4; i++) {
        int k0 = 4 * (lane + 32 * i);
        float a[4] = {v[i].x * sc, v[i].y * sc, v[i].z * sc, v[i].w * sc};
        unsigned short hs[4];
#pragma unroll
        for (int j = 0; j < 4; j++) hs[j] = __half_as_ushort(__float2half_rn(a[j]));
        *(ushort4*)(rp + k0) = make_ushort4(hs[0], hs[1], hs[2], hs[3]);
    }
}

// ---------------- K2: W^T aug split ----------------
__global__ void k_wprep(const float* __restrict__ W) {
    int n = blockIdx.x;
    for (int k = threadIdx.x; k < Dn; k += 256) {
        float w = W[(size_t)k * Dn + n];
        __half hh = __float2half_rn(w);
        unsigned short h = __half_as_ushort(hh);
        unsigned short m = __half_as_ushort(__float2half_rn(w - __half2float(hh)));
        size_t base = (size_t)n * KP;
        g_Wt[base + k] = h; g_Wt[base + 512 + k] = m; g_Wt[base + 1024 + k] = h;
    }
}

// ---------------- HMMA engine: C[256x128] = A[256xKA] * B[128xKA]^T, 512 thr ----------------
__device__ __forceinline__ void load_stage2(const unsigned short* Ab, const unsigned short* Bb,
                                            int KA, uint32_t sA, uint32_t sB, int kb, int tid) {
#pragma unroll
    for (int i = 0; i < 4; i++) {
        int u = tid + 512 * i, r = u >> 3, c = u & 7;
        int off = r * 128 + c * 16; off ^= (off >> 3) & 0x70;
        cp16(sA + off, Ab + (size_t)r * KA + kb + c * 8);
    }
#pragma unroll
    for (int i = 0; i < 2; i++) {
        int u = tid + 512 * i, r = u >> 3, c = u & 7;
        int off = r * 128 + c * 16; off ^= (off >> 3) & 0x70;
        cp16(sB + off, Bb + (size_t)r * KA + kb + c * 8);
    }
}

template<int NST>
__device__ __forceinline__ void gemm_tile(const unsigned short* Ab, const unsigned short* Bb,
                                          int KA, uint32_t smb, int tid, float acc[2][8][4]) {
    const int lane = tid & 31, w = tid >> 5;
    const int wr = w >> 1, wc = w & 1;
#pragma unroll
    for (int mi = 0; mi < 2; mi++)
#pragma unroll
        for (int ni = 0; ni < 8; ni++)
#pragma unroll
            for (int d = 0; d < 4; d++) acc[mi][ni][d] = 0.f;

    const int la = lane & 15, ka = (lane >> 4) * 16;
    uint32_t pA[2]; int xa[2];
#pragma unroll
    for (int mi = 0; mi < 2; mi++) {
        int row = wr * 32 + mi * 16 + la;
        pA[mi] = row * 128; xa[mi] = (row & 7) << 4;
    }
    const int lb = (lane & 7) + ((lane >> 4) & 1) * 8, kbB = ((lane >> 3) & 1) * 16;
    uint32_t pB[4]; int xb[4];
#pragma unroll
    for (int g = 0; g < 4; g++) {
        int row = wc * 64 + g * 16 + lb;
        pB[g] = row * 128; xb[g] = (row & 7) << 4;
    }

    load_stage2(Ab, Bb, KA, smb, smb + A_BYTES, 0, tid);
    CP_COMMIT();
    load_stage2(Ab, Bb, KA, smb + STG_BYTES, smb + STG_BYTES + A_BYTES, 64, tid);
    CP_COMMIT();
    for (int s = 0; s < NST; ++s) {
        CP_WAIT1();
        __syncthreads();
        if (s + 2 < NST) {
            int nb = (s + 2) % 3;
            load_stage2(Ab, Bb, KA, smb + nb * STG_BYTES,
                        smb + nb * STG_BYTES + A_BYTES, (s + 2) * 64, tid);
        }
        CP_COMMIT();
        const uint32_t sA = smb + (s % 3) * STG_BYTES;
        const uint32_t sB = sA + A_BYTES;
#pragma unroll
        for (int kk = 0; kk < 4; kk++) {
            const int kb = kk * 32;
            uint32_t a[2][4], bf[4][4];
#pragma unroll
            for (int mi = 0; mi < 2; mi++)
                ldm_x4(sA + pA[mi] + ((kb + ka) ^ xa[mi]),
                       a[mi][0], a[mi][1], a[mi][2], a[mi][3]);
#pragma unroll
            for (int g = 0; g < 4; g++)
                ldm_x4(sB + pB[g] + ((kb + kbB) ^ xb[g]),
                       bf[g][0], bf[g][1], bf[g][2], bf[g][3]);
#pragma unroll
            for (int mi = 0; mi < 2; mi++)
#pragma unroll
                for (int ni = 0; ni < 8; ni++) {
                    const int g = ni >> 1, p = ni & 1;
                    mma16816(acc[mi][ni], a[mi], bf[g][p * 2], bf[g][p * 2 + 1]);
                }
        }
    }
}

// ---------------- K3a: hi-only scores GEMM -> g_SCh (fp16) + per-row approx max ----------------
__global__ __launch_bounds__(512, 1) void k_scores_hi() {
    extern __shared__ char smx[];
    const int n0 = blockIdx.x * BN, m0 = blockIdx.y * BM, b = blockIdx.z;
    const int tid = threadIdx.x, lane = tid & 31, w = tid >> 5;
    const int wr = w >> 1, wc = w & 1;
    float acc[2][8][4];
    gemm_tile<8>(g_S + ((size_t)(b * T2 + m0)) * 512,
                 g_Dm + ((size_t)(b * T2 + n0)) * 512, 512, smem_u32(smx), tid, acc);
#pragma unroll
    for (int mi = 0; mi < 2; mi++) {
#pragma unroll
        for (int hi = 0; hi < 2; hi++) {
            int row = m0 + wr * 32 + mi * 16 + (lane >> 2) + hi * 8;
            __half* SCr = g_SCh + ((size_t)(b * T2) + row) * T2 + n0 + wc * 64 + 2 * (lane & 3);
            float rmax = -FLT_MAX;
#pragma unroll
            for (int ni = 0; ni < 8; ni++) {
                float v0 = acc[mi][ni][hi * 2], v1 = acc[mi][ni][hi * 2 + 1];
                rmax = fmaxf(rmax, fmaxf(v0, v1));
                *(__half2*)(SCr + ni * 8) = __floats2half2_rn(v0, v1);
            }
#pragma unroll
            for (int o = 1; o <= 2; o <<= 1)
                rmax = fmaxf(rmax, __shfl_xor_sync(0xFFFFFFFFu, rmax, o));
            if ((lane & 3) == 0) {
                unsigned u = __float_as_uint(rmax);
                u = (u & 0x80000000u) ? ~u : (u | 0x80000000u);
                atomicMax(&g_rmax[b * T2 + row], u);
            }
        }
    }
}

// ---------------- K3b: exact candidate rescore (1 warp / src row, half2 scan) ----------------
__global__ void k_cand(const float* __restrict__ x) {
    const int b = blockIdx.y;
    const int w = threadIdx.x >> 5;
    const int m = blockIdx.x * 8 + w;
    const int lane = threadIdx.x & 31;
    __shared__ int s_cnt[8];
    __shared__ int s_buf[8][CAND_CAP];
    if (lane == 0) s_cnt[w] = 0;
    __syncwarp();
    const __half* SC = g_SCh + ((size_t)(b * T2) + m) * T2;
    unsigned rm = g_rmax[b * T2 + m];
    float rmax = __uint_as_float((rm & 0x80000000u) ? (rm & 0x7FFFFFFFu) : ~rm);
    float thr = rmax - 1.024f;   // 1e-3 corr units at scale 2^10
#pragma unroll
    for (int c0 = 0; c0 < T2; c0 += 256) {
        const __half2* p = (const __half2*)(SC + c0 + lane * 8);
        __half2 h0 = p[0], h1 = p[1], h2 = p[2], h3 = p[3];
        __half2 mm = __hmax2(__hmax2(h0, h1), __hmax2(h2, h3));
        float mx = fmaxf(__low2float(mm), __high2float(mm));
        if (__ballot_sync(0xFFFFFFFFu, mx >= thr)) {
            if (mx >= thr) {
                float v[8] = {__low2float(h0), __high2float(h0), __low2float(h1), __high2float(h1),
                              __low2float(h2), __high2float(h2), __low2float(h3), __high2float(h3)};
#pragma unroll
                for (int j = 0; j < 8; j++)
                    if (v[j] >= thr) {
                        int idx = atomicAdd(&s_cnt[w], 1);
                        if (idx < CAND_CAP) s_buf[w][idx] = c0 + lane * 8 + j;
                    }
            }
        }
    }
    __syncwarp();
    int cnt = min(s_cnt[w], CAND_CAP);
    const float* xb = x + (size_t)b * Tn * Dn;
    const float* xs = xb + (size_t)(2 * m + 1) * Dn;
    const float inv_s = g_inv[b * Tn + 2 * m + 1];
    float best = -FLT_MAX; int bcol = 0x7FFFFFFF;
    for (int c = 0; c < cnt; c++) {
        int j = s_buf[w][c];
        const float* xd = xb + (size_t)(2 * j) * Dn;
        float acc = 0.f;
#pragma unroll
        for (int i = 0; i < 4; i++) {
            int k = lane * 4 + i * 128;
            float4 a = *(const float4*)(xs + k);
            float4 d = *(const float4*)(xd + k);
            acc += a.x * d.x + a.y * d.y + a.z * d.z + a.w * d.w;
        }
#pragma unroll
        for (int o = 16; o; o >>= 1) acc += __shfl_xor_sync(0xFFFFFFFFu, acc, o);
        float e = acc * inv_s * g_inv[b * Tn + 2 * j];
        if (e > best || (e == best && j < bcol)) { best = e; bcol = j; }
    }
    if (lane == 0) {
        unsigned u = __float_as_uint(best);
        u = (u & 0x80000000u) ? ~u : (u | 0x80000000u);
        g_key[b * T2 + m] = ((unsigned long long)u << 32) | (unsigned)(2047 - bcol);
    }
}

// ---------------- K4: bitonic top-k ----------------
__global__ void k_topk() {
    const int b = blockIdx.x;
    __shared__ unsigned long long keys[T2];
    const int tid = threadIdx.x;
    g_winner[b * T2 + tid] = -1;
    g_winner[b * T2 + tid + 1024] = -1;
    for (int t = tid; t < Tn; t += 1024) g_merged[b * Tn + t] = 0;
    for (int i = tid; i < T2; i += 1024) {
        unsigned long long kv = g_key[b * T2 + i];
        unsigned mono = (unsigned)(kv >> 32);
        g_barg[b * T2 + i] = 2047 - (int)(kv & 0xFFFFFFFFu);
        keys[i] = ((unsigned long long)(~mono) << 32) | (unsigned)i;
    }
    __syncthreads();
    for (int k2 = 2; k2 <= T2; k2 <<= 1) {
        for (int j = k2 >> 1; j > 0; j >>= 1) {
            for (int i = tid; i < T2; i += 1024) {
                int ixj = i ^ j;
                if (ixj > i) {
                    bool up = ((i & k2) == 0);
                    unsigned long long a = keys[i], c = keys[ixj];
                    if ((a > c) == up) { keys[i] = c; keys[ixj] = a; }
                }
            }
            __syncthreads();
        }
    }
    if (tid < Rn) {
        int s = (int)(keys[tid] & 0xFFFFFFFFu);
        int stok = 2 * s + 1;
        int dloc = g_barg[b * T2 + s];
        g_srctok[b * Rn + tid] = stok;
        g_dsttok[b * Rn + tid] = 2 * dloc;
        g_merged[b * Tn + stok] = 1;
        atomicMax(&g_winner[b * T2 + dloc], tid);
    }
}

// ---------------- K5: compaction ----------------
__global__ void k_scan() {
    const int b = blockIdx.x;
    __shared__ int sums[1024];
    const int tid = threadIdx.x;
    const int base = tid * 4;
    int loc[4]; int c0 = 0;
#pragma unroll
    for (int i = 0; i < 4; i++) { loc[i] = g_merged[b * Tn + base + i] ? 0 : 1; c0 += loc[i]; }
    sums[tid] = c0; __syncthreads();
    for (int off = 1; off < 1024; off <<= 1) {
        int v = (tid >= off) ? sums[tid - off] : 0;
        __syncthreads();
        sums[tid] += v;
        __syncthreads();
    }
    int run = (tid == 0) ? 0 : sums[tid - 1];
#pragma unroll
    for (int i = 0; i < 4; i++)
        if (loc[i]) { g_col[b * Cn + run] = base + i; run++; }
}

// ---------------- K6: merged matrix, fp16 3-term split ----------------
__global__ void k_build2(const float* __restrict__ x) {
    const int b = blockIdx.y, c = blockIdx.x;
    const int t = g_col[b * Cn + c];
    const int tid = threadIdx.x; // 128
    const float* xb = x + (size_t)b * Tn * Dn;
    float4 v = *(const float4*)(xb + (size_t)t * Dn + tid * 4);
    if ((t & 1) == 0) {
        int w = g_winner[b * T2 + (t >> 1)];
        if (w >= 0) {
            int mt = g_srctok[b * Rn + w];
            float4 u = *(const float4*)(xb + (size_t)mt * Dn + tid * 4);
            v.x = (u.x + v.x) * 0.5f; v.y = (u.y + v.y) * 0.5f;
            v.z = (u.z + v.z) * 0.5f; v.w = (u.w + v.w) * 0.5f;
        }
    }
    unsigned short* rp = g_A2 + ((size_t)(b * Cn + c)) * KP;
    float a[4] = {v.x, v.y, v.z, v.w};
    unsigned short hs[4], ms[4];
#pragma unroll
    for (int j = 0; j < 4; j++) {
        __half hh = __float2half_rn(a[j]);
        hs[j] = __half_as_ushort(hh);
        ms[j] = __half_as_ushort(__float2half_rn(a[j] - __half2float(hh)));
    }
    ushort4 h4 = make_ushort4(hs[0], hs[1], hs[2], hs[3]);
    ushort4 m4 = make_ushort4(ms[0], ms[1], ms[2], ms[3]);
    int k0 = tid * 4;
    *(ushort4*)(rp + k0)        = h4;
    *(ushort4*)(rp + 512 + k0)  = h4;
    *(ushort4*)(rp + 1024 + k0) = m4;
}

// ---------------- K7: hidden GEMM + scattered epilogue ----------------
__global__ __launch_bounds__(512, 1) void k_hidden_mma(const float* __restrict__ bias,
                                                       float* __restrict__ out) {
    extern __shared__ char smx[];
    const int n0 = blockIdx.x * BN, m0 = blockIdx.y * BM;
    const int b = m0 / Cn, cm0 = m0 % Cn;
    const int tid = threadIdx.x, lane = tid & 31, w = tid >> 5;
    const int wr = w >> 1, wc = w & 1;
    int*   s_tok  = (int*)(smx + 3 * STG_BYTES);
    float* s_bias = (float*)(smx + 3 * STG_BYTES + 1024);
    if (tid < 256) s_tok[tid] = g_col[b * Cn + cm0 + tid];
    if (tid >= 256 && tid < 384) s_bias[tid - 256] = bias[n0 + tid - 256];
    __syncthreads();
    float acc[2][8][4];
    gemm_tile<24>(g_A2 + (size_t)m0 * KP, g_Wt + (size_t)n0 * KP, KP, smem_u32(smx), tid, acc);
#pragma unroll
    for (int mi = 0; mi < 2; mi++) {
#pragma unroll
        for (int hi = 0; hi < 2; hi++) {
            int row = wr * 32 + mi * 16 + (lane >> 2) + hi * 8;
            int tok = s_tok[row];
            float* op = out + (size_t)b * Tn * Dn + (size_t)tok * Dn + n0;
#pragma unroll
            for (int ni = 0; ni < 8; ni++) {
                int col = wc * 64 + ni * 8 + 2 * (lane & 3);
                float2 o;
                o.x = acc[mi][ni][hi * 2 + 0] + s_bias[col + 0];
                o.y = acc[mi][ni][hi * 2 + 1] + s_bias[col + 1];
                *(float2*)(op + col) = o;
            }
        }
    }
}

// ---------------- K8: out[src] = out[dst] ----------------
__global__ void k_copy(float* __restrict__ out) {
    const int b = blockIdx.y, i = blockIdx.x;
    const int st = g_srctok[b * Rn + i], dt = g_dsttok[b * Rn + i];
    const int tid = threadIdx.x; // 128
    const float4* src = (const float4*)(out + (size_t)b * Tn * Dn + (size_t)dt * Dn);
    float4* dst = (float4*)(out + (size_t)b * Tn * Dn + (size_t)st * Dn);
    dst[tid] = src[tid];
}

extern "C" void kernel_launch(void* const* d_in, const int* in_sizes, int n_in,
                              void* d_out, int out_size) {
    const float* x    = (const float*)d_in[0];
    const float* W    = (const float*)d_in[1];
    const float* bias = (const float*)d_in[2];
    float* out = (float*)d_out;

    static int cfg = 0;
    if (!cfg) {
        cudaFuncSetAttribute(k_scores_hi, cudaFuncAttributeMaxDynamicSharedMemorySize, SMEM_DYN);
        cudaFuncSetAttribute(k_hidden_mma, cudaFuncAttributeMaxDynamicSharedMemorySize, SMEM_DYN);
        cfg = 1;
    }

    k_prep<<<Bn * Tn / 8, 256>>>(x);
    k_wprep<<<Dn, 256>>>(W);
    k_scores_hi<<<dim3(T2 / BN, T2 / BM, Bn), 512, SMEM_DYN>>>();
    k_cand<<<dim3(T2 / 8, Bn), 256>>>(x);
    k_topk<<<Bn, 1024>>>();
    k_scan<<<Bn, 1024>>>();
    k_build2<<<dim3(Cn, Bn), 128>>>(x);
    k_hidden_mma<<<dim3(Dn / BN, (Bn * Cn) / BM), 512, SMEM_DYN>>>(bias, out);
    k_copy<<<dim3(Rn, Bn), 128>>>(out);
}